// round 1
// baseline (speedup 1.0000x reference)
#include <cuda_runtime.h>

#define GRIDSZ 32
#define BATCH  16
#define NPTS   131072
#define GCELLS (GRIDSZ * GRIDSZ * GRIDSZ)   // 32768
#define PPT    4                            // points per thread
#define TPB    256

// Scratch (allocation-free rule: __device__ globals)
__device__ float4 g_closest4[BATCH * GCELLS];     // 8 MB repacked gather table
__device__ float  g_consts[BATCH * 6 * 12];       // per-(batch,transform) constants

// ---------------------------------------------------------------------------
// Kernel 1: zero output scalar + precompute transform constants.
//   planes j<3 : slot = {n0,n1,n2,d, a0,a1,a2}  with a = 2*n/(n·n)
//   quats  j>=3: slot = fused 3x3 matrix M = (1/||q||) * [ (w^2-|v|^2) I + 2 v v^T + 2 w [v]x ]
// ---------------------------------------------------------------------------
__global__ void precompute_kernel(const float* __restrict__ out6, float* __restrict__ d_out) {
    int t = threadIdx.x;
    if (t == 0) *d_out = 0.0f;
    if (t >= BATCH * 6) return;
    int b = t / 6, j = t % 6;
    const float* q = out6 + (b * 6 + j) * 4;
    float* c = g_consts + (b * 6 + j) * 12;
    float q0 = q[0], q1 = q[1], q2 = q[2], q3 = q[3];
    if (j < 3) {
        float inv = 1.0f / (q0 * q0 + q1 * q1 + q2 * q2);
        c[0] = q0; c[1] = q1; c[2] = q2; c[3] = q3;
        c[4] = 2.0f * q0 * inv;
        c[5] = 2.0f * q1 * inv;
        c[6] = 2.0f * q2 * inv;
    } else {
        float w = q0, x = q1, y = q2, z = q3;
        float vv = x * x + y * y + z * z;
        float s = rsqrtf(w * w + vv);          // 1/||q||
        float ww = w * w - vv;
        c[0] = s * (ww + 2.0f * x * x);
        c[1] = s * 2.0f * (x * y - w * z);
        c[2] = s * 2.0f * (x * z + w * y);
        c[3] = s * 2.0f * (x * y + w * z);
        c[4] = s * (ww + 2.0f * y * y);
        c[5] = s * 2.0f * (y * z - w * x);
        c[6] = s * 2.0f * (x * z - w * y);
        c[7] = s * 2.0f * (y * z + w * x);
        c[8] = s * (ww + 2.0f * z * z);
    }
}

// ---------------------------------------------------------------------------
// Kernel 2: repack closest (B,G,3) fp32 -> 16B-aligned float4 table so every
// random gather is a single LDG.128 hitting exactly one 32B sector.
// ---------------------------------------------------------------------------
__global__ void repack_kernel(const float* __restrict__ closest) {
    int i = blockIdx.x * blockDim.x + threadIdx.x;
    if (i < BATCH * GCELLS) {
        const float* p = closest + (size_t)i * 3;
        g_closest4[i] = make_float4(p[0], p[1], p[2], 0.0f);
    }
}

// ---------------------------------------------------------------------------
// Kernel 3: main. grid = (NPTS/(TPB*PPT), BATCH). One CTA column per batch.
// ---------------------------------------------------------------------------
__global__ void __launch_bounds__(TPB)
sym_loss_kernel(const float* __restrict__ points, float* __restrict__ d_out) {
    __shared__ float sc[72];
    __shared__ float wsum[TPB / 32];

    const int b = blockIdx.y;
    if (threadIdx.x < 72) sc[threadIdx.x] = g_consts[b * 72 + threadIdx.x];
    __syncthreads();

    const float4* __restrict__ ctab = g_closest4 + b * GCELLS;
    const float* __restrict__ pbase = points + (size_t)b * NPTS * 3;
    const int base = blockIdx.x * (TPB * PPT) + threadIdx.x;

    float acc = 0.0f;

#pragma unroll
    for (int k = 0; k < PPT; k++) {
        const int n = base + k * TPB;
        const float px = pbase[n * 3 + 0];
        const float py = pbase[n * 3 + 1];
        const float pz = pbase[n * 3 + 2];

        float sx[6], sy[6], sz[6];
        // 3 reflections
#pragma unroll
        for (int j = 0; j < 3; j++) {
            const float* c = sc + j * 12;
            float t = fmaf(c[0], px, fmaf(c[1], py, fmaf(c[2], pz, c[3])));
            sx[j] = fmaf(-t, c[4], px);
            sy[j] = fmaf(-t, c[5], py);
            sz[j] = fmaf(-t, c[6], pz);
        }
        // 3 quaternion rotations (fused scaled matrices)
#pragma unroll
        for (int j = 0; j < 3; j++) {
            const float* m = sc + (3 + j) * 12;
            sx[3 + j] = fmaf(m[0], px, fmaf(m[1], py, m[2] * pz));
            sy[3 + j] = fmaf(m[3], px, fmaf(m[4], py, m[5] * pz));
            sz[3 + j] = fmaf(m[6], px, fmaf(m[7], py, m[8] * pz));
        }

        // cell indices (clamp to [0,32], trunc, clip to 31)
        int fl[6];
#pragma unroll
        for (int j = 0; j < 6; j++) {
            float cx = fminf(fmaxf(sx[j], 0.0f), 32.0f);
            float cy = fminf(fmaxf(sy[j], 0.0f), 32.0f);
            float cz = fminf(fmaxf(sz[j], 0.0f), 32.0f);
            int ix = min((int)cx, GRIDSZ - 1);
            int iy = min((int)cy, GRIDSZ - 1);
            int iz = min((int)cz, GRIDSZ - 1);
            fl[j] = (ix << 10) + (iy << 5) + iz;
        }

        // batch the 6 independent gathers for MLP
        float4 cp[6];
#pragma unroll
        for (int j = 0; j < 6; j++) cp[j] = __ldg(&ctab[fl[j]]);

#pragma unroll
        for (int j = 0; j < 6; j++) {
            float dx = sx[j] - cp[j].x;
            float dy = sy[j] - cp[j].y;
            float dz = sz[j] - cp[j].z;
            acc += sqrtf(fmaf(dx, dx, fmaf(dy, dy, dz * dz)));
        }
    }

    // warp reduce
#pragma unroll
    for (int o = 16; o > 0; o >>= 1)
        acc += __shfl_down_sync(0xffffffffu, acc, o);
    if ((threadIdx.x & 31) == 0) wsum[threadIdx.x >> 5] = acc;
    __syncthreads();
    if (threadIdx.x == 0) {
        float s = 0.0f;
#pragma unroll
        for (int w = 0; w < TPB / 32; w++) s += wsum[w];
        atomicAdd(d_out, s * (1.0f / BATCH));
    }
}

// ---------------------------------------------------------------------------
extern "C" void kernel_launch(void* const* d_in, const int* in_sizes, int n_in,
                              void* d_out, int out_size) {
    const float* output  = nullptr;
    const float* points  = nullptr;
    const float* closest = nullptr;
    for (int i = 0; i < n_in; i++) {
        if (in_sizes[i] == BATCH * 6 * 4)       output  = (const float*)d_in[i];
        else if (in_sizes[i] == BATCH * NPTS * 3)  points  = (const float*)d_in[i];
        else if (in_sizes[i] == BATCH * GCELLS * 3) closest = (const float*)d_in[i];
    }

    precompute_kernel<<<1, 96>>>(output, (float*)d_out);
    repack_kernel<<<(BATCH * GCELLS + 255) / 256, 256>>>(closest);

    dim3 grid(NPTS / (TPB * PPT), BATCH);
    sym_loss_kernel<<<grid, TPB>>>(points, (float*)d_out);
}